// round 2
// baseline (speedup 1.0000x reference)
#include <cuda_runtime.h>
#include <cuda_bf16.h>

// Problem: B=8, N=2048, F=D=128
//   H = A_hat @ X          (per batch, 2048x2048 @ 2048x128)
//   O = H @ W^T + b        (W is [D,F] row-major, torch Linear)
//   out = relu(LN(O) * gamma + beta)
//
// Plan:
//   k0: transpose W -> g_Wt[f*128+d]   (tiny)
//   k1: tiled fp32 SGEMM A@X -> g_H    (dominant cost)
//   k2: fused GEMM2 + bias + LayerNorm + ReLU -> out

#define BATCH 8
#define NN    2048
#define FF    128
#define DD    128

// ---------------- scratch (no allocs allowed) ----------------
__device__ float g_H[BATCH * NN * FF];   // 8 MB
__device__ float g_Wt[FF * DD];          // W transposed: [f][d]

// ---------------- k0: transpose W ----------------
__global__ void wt_kernel(const float* __restrict__ W) {
    int i = blockIdx.x * blockDim.x + threadIdx.x;   // 0..16383
    int d = i >> 7;          // /128
    int f = i & 127;
    g_Wt[f * DD + d] = W[d * FF + f];
}

// ---------------- k1: H = A @ X ----------------
// grid: (16 row-tiles, 8 batches), block: 256 threads
// tile: BM=128 rows x BF=128 cols, BK=32 k-chunk, 8x8 microtile/thread
#define BM 128
#define BK 32
#define BF 128

__global__ __launch_bounds__(256, 1)
void gemm1_kernel(const float* __restrict__ A, const float* __restrict__ X) {
    const int bt      = blockIdx.y;
    const int rowTile = blockIdx.x;

    const float* Ab = A + (size_t)bt * NN * NN + (size_t)rowTile * BM * NN;
    const float* Xb = X + (size_t)bt * NN * FF;
    float*       Hb = g_H + (size_t)bt * NN * FF + (size_t)rowTile * BM * FF;

    __shared__ float sA[BK][BM + 4];   // A staged transposed [k][m]
    __shared__ float sX[BK][BF];       // X staged [k][f]

    const int tid = threadIdx.x;
    const int tx  = tid & 15;          // 0..15  -> f
    const int ty  = tid >> 4;          // 0..15  -> m

    float acc[8][8];
#pragma unroll
    for (int i = 0; i < 8; i++)
#pragma unroll
        for (int j = 0; j < 8; j++) acc[i][j] = 0.f;

    for (int k0 = 0; k0 < NN; k0 += BK) {
        // ---- load A tile: 128 rows x 32 cols = 1024 float4, 4 per thread ----
#pragma unroll
        for (int i = 0; i < 4; i++) {
            int idx = tid + i * 256;        // 0..1023
            int row = idx >> 3;             // 0..127
            int c4  = idx & 7;              // float4 within row
            float4 v = *(const float4*)(Ab + (size_t)row * NN + k0 + c4 * 4);
            sA[c4 * 4 + 0][row] = v.x;
            sA[c4 * 4 + 1][row] = v.y;
            sA[c4 * 4 + 2][row] = v.z;
            sA[c4 * 4 + 3][row] = v.w;
        }
        // ---- load X tile: 32 rows x 128 cols = 1024 float4, 4 per thread ----
#pragma unroll
        for (int i = 0; i < 4; i++) {
            int idx = tid + i * 256;
            int row = idx >> 5;             // k 0..31
            int c4  = idx & 31;
            *(float4*)&sX[row][c4 * 4] =
                *(const float4*)(Xb + (size_t)(k0 + row) * FF + c4 * 4);
        }
        __syncthreads();

#pragma unroll
        for (int k = 0; k < BK; k++) {
            float ra[8], rb[8];
#pragma unroll
            for (int i = 0; i < 4; i++) {
                *(float2*)&ra[i * 2] = *(const float2*)&sA[k][ty * 8 + i * 2];
            }
            *(float4*)&rb[0] = *(const float4*)&sX[k][tx * 8];
            *(float4*)&rb[4] = *(const float4*)&sX[k][tx * 8 + 4];
#pragma unroll
            for (int i = 0; i < 8; i++)
#pragma unroll
                for (int j = 0; j < 8; j++) acc[i][j] += ra[i] * rb[j];
        }
        __syncthreads();
    }

    // ---- write H tile ----
#pragma unroll
    for (int i = 0; i < 8; i++) {
        float* dst = Hb + (size_t)(ty * 8 + i) * FF + tx * 8;
        *(float4*)(dst + 0) = *(float4*)&acc[i][0];
        *(float4*)(dst + 4) = *(float4*)&acc[i][4];
    }
}

// ---------------- k2: O = H@W^T + b, LN, ReLU ----------------
// grid: 16384/64 = 256 CTAs; block 256. Each CTA: 64 rows, all 128 d.
// thread (ty,tx): rows ty*4..ty*4+3, cols d = tx*8..tx*8+7
#define BM2 64

__global__ __launch_bounds__(256, 2)
void gemm2_ln_kernel(const float* __restrict__ bias,
                     const float* __restrict__ gamma,
                     const float* __restrict__ beta,
                     float* __restrict__ out) {
    __shared__ float sH[BM2 * FF];      // 32 KB
    __shared__ float sW[32 * DD];       // 16 KB  (Wt chunk: [f][d])

    const int tid = threadIdx.x;
    const int tx  = tid & 15;
    const int ty  = tid >> 4;
    const size_t rowBase = (size_t)blockIdx.x * BM2;

    // load H rows: 64*128 floats = 2048 float4, 8 per thread
#pragma unroll
    for (int i = 0; i < 8; i++) {
        int idx = tid + i * 256;
        int r   = idx >> 5;
        int c4  = idx & 31;
        *(float4*)&sH[r * FF + c4 * 4] =
            *(const float4*)(g_H + (rowBase + r) * FF + c4 * 4);
    }

    float acc[4][8];
#pragma unroll
    for (int r = 0; r < 4; r++)
#pragma unroll
        for (int j = 0; j < 8; j++) acc[r][j] = 0.f;

    for (int fc = 0; fc < FF; fc += 32) {
        // load Wt chunk [32][128]: 1024 float4, 4 per thread (coalesced, from g_Wt)
#pragma unroll
        for (int i = 0; i < 4; i++) {
            int idx = tid + i * 256;
            int fr  = idx >> 5;
            int c4  = idx & 31;
            *(float4*)&sW[fr * DD + c4 * 4] =
                *(const float4*)(g_Wt + (size_t)(fc + fr) * DD + c4 * 4);
        }
        __syncthreads();

#pragma unroll
        for (int f = 0; f < 32; f++) {
            float rw[8];
            *(float4*)&rw[0] = *(const float4*)&sW[f * DD + tx * 8];
            *(float4*)&rw[4] = *(const float4*)&sW[f * DD + tx * 8 + 4];
#pragma unroll
            for (int r = 0; r < 4; r++) {
                float h = sH[(ty * 4 + r) * FF + fc + f];
#pragma unroll
                for (int j = 0; j < 8; j++) acc[r][j] += h * rw[j];
            }
        }
        __syncthreads();
    }

    // bias
    float bb[8], gg[8], be[8];
    *(float4*)&bb[0] = *(const float4*)(bias  + tx * 8);
    *(float4*)&bb[4] = *(const float4*)(bias  + tx * 8 + 4);
    *(float4*)&gg[0] = *(const float4*)(gamma + tx * 8);
    *(float4*)&gg[4] = *(const float4*)(gamma + tx * 8 + 4);
    *(float4*)&be[0] = *(const float4*)(beta  + tx * 8);
    *(float4*)&be[4] = *(const float4*)(beta  + tx * 8 + 4);

#pragma unroll
    for (int r = 0; r < 4; r++)
#pragma unroll
        for (int j = 0; j < 8; j++) acc[r][j] += bb[j];

    // LayerNorm over d (128 values per row, spread across 16 tx lanes, 8 each)
#pragma unroll
    for (int r = 0; r < 4; r++) {
        float s = 0.f, s2 = 0.f;
#pragma unroll
        for (int j = 0; j < 8; j++) { s += acc[r][j]; s2 += acc[r][j] * acc[r][j]; }
        // reduce across the 16 tx lanes (same ty -> contiguous lanes within half-warp)
#pragma unroll
        for (int off = 8; off >= 1; off >>= 1) {
            s  += __shfl_xor_sync(0xffffffffu, s,  off);
            s2 += __shfl_xor_sync(0xffffffffu, s2, off);
        }
        float mean = s * (1.0f / 128.0f);
        float var  = s2 * (1.0f / 128.0f) - mean * mean;
        float inv  = rsqrtf(var + 1e-5f);

        float o[8];
#pragma unroll
        for (int j = 0; j < 8; j++) {
            float v = (acc[r][j] - mean) * inv * gg[j] + be[j];
            o[j] = fmaxf(v, 0.f);
        }
        float* dst = out + (rowBase + ty * 4 + r) * DD + tx * 8;
        *(float4*)(dst + 0) = *(float4*)&o[0];
        *(float4*)(dst + 4) = *(float4*)&o[4];
    }
}

// ---------------- launch ----------------
extern "C" void kernel_launch(void* const* d_in, const int* in_sizes, int n_in,
                              void* d_out, int out_size) {
    const float* A     = (const float*)d_in[0];   // [8,2048,2048]
    const float* X     = (const float*)d_in[1];   // [8,2048,128]
    const float* W     = (const float*)d_in[2];   // [128,128]
    const float* bias  = (const float*)d_in[3];   // [128]
    const float* gamma = (const float*)d_in[4];   // [128]
    const float* beta  = (const float*)d_in[5];   // [128]
    float* out = (float*)d_out;                   // [8,2048,128]

    wt_kernel<<<64, 256>>>(W);
    gemm1_kernel<<<dim3(16, 8), 256>>>(A, X);
    gemm2_ln_kernel<<<(BATCH * NN) / BM2, 256>>>(bias, gamma, beta, out);
}

// round 4
// speedup vs baseline: 3.4403x; 3.4403x over previous
#include <cuda_runtime.h>
#include <cstdint>

// B=8, N=2048, F=D=128
//   H = A_hat @ X ; O = H @ W^T + b ; out = relu(LN(O)*gamma+beta)
//
// tcgen05 is rejected by the harness toolchain (targets base sm_103), so the
// tensor path is mma.sync.m16n8k8 tf32 (sm_80+ PTX -> HMMA on the tensor pipe).
//
// k0: xt_kernel  X[b,k,f] -> g_Xt[b,f,k]
// k1: fused_kernel (128 CTAs, 256 thr): 4-stage cp.async pipeline over K=2048,
//     GEMM1 in register accumulators -> H to smem -> GEMM2 vs W -> bias+LN+ReLU.

#define BATCH 8
#define NN    2048
#define FF    128

#define PADA  36            // floats per row, stage tiles (128x32 + pad)
#define PADH  132           // floats per row, H / W tiles (128x128 + pad)

#define ST_X_OFF   18432    // X tile offset within a stage (A tile is 18432 B)
#define STAGE_B    36864    // bytes per stage
#define SM_W_OFF   69632    // W tile (overlays pipe region post-mainloop)
#define SM_PAR_OFF 147456   // bias | gamma | beta (3 x 512 B)
#define SM_RED_OFF 148992   // LN partials: 128 rows x {wn0,wn1} x {s1,s2}
#define SM_TOTAL   151040

__device__ __align__(16) float g_Xt[BATCH * FF * NN];   // 8 MB scratch

__device__ __forceinline__ uint32_t smem_u32(const void* p) {
    uint32_t a;
    asm("{ .reg .u64 t; cvta.to.shared.u64 t, %1; cvt.u32.u64 %0, t; }" : "=r"(a) : "l"(p));
    return a;
}
__device__ __forceinline__ void cp16(uint32_t dst, const void* src) {
    asm volatile("cp.async.cg.shared.global [%0], [%1], 16;" :: "r"(dst), "l"(src) : "memory");
}
#define CP_COMMIT() asm volatile("cp.async.commit_group;" ::: "memory")

// m16n8k8 tf32: a=4 regs, b=2 regs, c/d=4 f32. Raw fp32 bits in a/b (HW uses
// top 10 mantissa bits; the uniform relative bias cancels under LayerNorm).
#define MMA_TF32(d, av, bv)                                                     \
    asm volatile("mma.sync.aligned.m16n8k8.row.col.f32.tf32.tf32.f32 "          \
        "{%0,%1,%2,%3}, {%4,%5,%6,%7}, {%8,%9}, {%0,%1,%2,%3};"                 \
        : "+f"((d)[0]), "+f"((d)[1]), "+f"((d)[2]), "+f"((d)[3])                \
        : "r"((av)[0]), "r"((av)[1]), "r"((av)[2]), "r"((av)[3]),               \
          "r"((bv)[0]), "r"((bv)[1]))

// ---------------- k0: X transpose -> g_Xt[b][f][k] ----------------
__global__ void xt_kernel(const float* __restrict__ X) {
    __shared__ float t[32][33];
    int b = blockIdx.z;
    int k0 = blockIdx.x * 32, f0 = blockIdx.y * 32;
    int tx = threadIdx.x & 31, ty = threadIdx.x >> 5;   // ty 0..7
    const float* Xb = X + (size_t)b * NN * FF;
#pragma unroll
    for (int i = 0; i < 4; i++)
        t[ty + i * 8][tx] = Xb[(size_t)(k0 + ty + i * 8) * FF + f0 + tx];
    __syncthreads();
    float* Ob = g_Xt + (size_t)b * FF * NN;
#pragma unroll
    for (int i = 0; i < 4; i++)
        Ob[(size_t)(f0 + ty + i * 8) * NN + k0 + tx] = t[tx][ty + i * 8];
}

// ---------------- k1: fused ----------------
__global__ __launch_bounds__(256, 1)
void fused_kernel(const float* __restrict__ A, const float* __restrict__ W,
                  const float* __restrict__ bias, const float* __restrict__ gamma,
                  const float* __restrict__ beta, float* __restrict__ out) {
    extern __shared__ char smem[];
    float* sf = (float*)smem;
    const uint32_t sbu = smem_u32(smem);

    const int tid = threadIdx.x;
    const int lid = tid & 31;
    const int wid = tid >> 5;
    const int gp  = lid >> 2;        // groupID (row within fragment)
    const int tg  = lid & 3;         // thread-in-group (k within fragment)
    const int wm  = wid >> 1;        // warp row 0..3  (32 rows each)
    const int wn  = wid & 1;         // warp col 0..1  (64 cols each)
    const int bt      = blockIdx.x >> 4;
    const int rowTile = blockIdx.x & 15;

    const float* Ab = A    + (size_t)bt * NN * NN + (size_t)rowTile * 128 * NN;
    const float* Xb = g_Xt + (size_t)bt * FF * NN;

    float acc[2][8][4];
#pragma unroll
    for (int i = 0; i < 2; i++)
#pragma unroll
        for (int j = 0; j < 8; j++)
#pragma unroll
            for (int k = 0; k < 4; k++) acc[i][j][k] = 0.f;

    // ---- pipeline loader: chunk c (32 k) -> stage c&3 ----
    auto load_chunk = [&](int c) {
        const int st = c & 3;
        const uint32_t ab = sbu + (uint32_t)st * STAGE_B;
        const uint32_t xb = ab + ST_X_OFF;
        const float* ga = Ab + c * 32;
        const float* gx = Xb + c * 32;
#pragma unroll
        for (int i = 0; i < 4; i++) {
            int id = tid + i * 256;              // 0..1023
            int r = id >> 3, q = id & 7;         // row 0..127, float4 0..7
            uint32_t off = (uint32_t)(r * PADA + q * 4) * 4u;
            cp16(ab + off, ga + (size_t)r * NN + q * 4);
            cp16(xb + off, gx + (size_t)r * NN + q * 4);
        }
        CP_COMMIT();
    };

    load_chunk(0); load_chunk(1); load_chunk(2);

    // ---- GEMM1 mainloop: 64 chunks of k=32 ----
    for (int c = 0; c < 64; c++) {
        const int st = c & 3;
        asm volatile("cp.async.wait_group 2;" ::: "memory");
        __syncthreads();
        if (c + 3 < 64) load_chunk(c + 3); else CP_COMMIT();  // uniform group count

        const uint32_t* sA = (const uint32_t*)(smem + st * STAGE_B);
        const uint32_t* sX = (const uint32_t*)(smem + st * STAGE_B + ST_X_OFF);
#pragma unroll
        for (int k8 = 0; k8 < 4; k8++) {
            const int kb = k8 * 8;
            uint32_t af[2][4], bf[8][2];
#pragma unroll
            for (int mt = 0; mt < 2; mt++) {
                int r0 = wm * 32 + mt * 16 + gp;
                const uint32_t* p0 = sA + r0 * PADA + kb + tg;
                const uint32_t* p1 = sA + (r0 + 8) * PADA + kb + tg;
                af[mt][0] = p0[0]; af[mt][2] = p0[4];
                af[mt][1] = p1[0]; af[mt][3] = p1[4];
            }
#pragma unroll
            for (int nt = 0; nt < 8; nt++) {
                int nc = wn * 64 + nt * 8 + gp;
                const uint32_t* p = sX + nc * PADA + kb + tg;
                bf[nt][0] = p[0]; bf[nt][1] = p[4];
            }
#pragma unroll
            for (int mt = 0; mt < 2; mt++)
#pragma unroll
                for (int nt = 0; nt < 8; nt++)
                    MMA_TF32(acc[mt][nt], af[mt], bf[nt]);
        }
    }

    asm volatile("cp.async.wait_group 0;" ::: "memory");
    __syncthreads();   // all compute done; pipe region may be overwritten

    // ---- H (regs) -> smem [128][132] at offset 0 ----
#pragma unroll
    for (int mt = 0; mt < 2; mt++)
#pragma unroll
        for (int nt = 0; nt < 8; nt++) {
            int r  = wm * 32 + mt * 16 + gp;
            int cc = wn * 64 + nt * 8 + 2 * tg;
            *(float2*)(sf + (size_t)r * PADH + cc) =
                make_float2(acc[mt][nt][0], acc[mt][nt][1]);
            *(float2*)(sf + (size_t)(r + 8) * PADH + cc) =
                make_float2(acc[mt][nt][2], acc[mt][nt][3]);
        }

    // ---- W [128][128] -> smem [128][132] ----
#pragma unroll
    for (int i = 0; i < 16; i++) {
        int id = tid + i * 256;                  // 0..4095 float4
        int d = id >> 5, q = id & 31;
        float4 v = *(const float4*)(W + (size_t)d * FF + q * 4);
        *(float4*)(sf + SM_W_OFF / 4 + (size_t)d * PADH + q * 4) = v;
    }
    if (tid < 128) {
        sf[SM_PAR_OFF / 4 + tid]       = bias[tid];
        sf[SM_PAR_OFF / 4 + 128 + tid] = gamma[tid];
        sf[SM_PAR_OFF / 4 + 256 + tid] = beta[tid];
    }
    __syncthreads();

    // ---- GEMM2: O = H @ W^T  (K = 128) ----
#pragma unroll
    for (int i = 0; i < 2; i++)
#pragma unroll
        for (int j = 0; j < 8; j++)
#pragma unroll
            for (int k = 0; k < 4; k++) acc[i][j][k] = 0.f;

    const uint32_t* sH = (const uint32_t*)(smem);
    const uint32_t* sW = (const uint32_t*)(smem + SM_W_OFF);
#pragma unroll
    for (int k8 = 0; k8 < 16; k8++) {
        const int kb = k8 * 8;
        uint32_t af[2][4], bf[8][2];
#pragma unroll
        for (int mt = 0; mt < 2; mt++) {
            int r0 = wm * 32 + mt * 16 + gp;
            const uint32_t* p0 = sH + r0 * PADH + kb + tg;
            const uint32_t* p1 = sH + (r0 + 8) * PADH + kb + tg;
            af[mt][0] = p0[0]; af[mt][2] = p0[4];
            af[mt][1] = p1[0]; af[mt][3] = p1[4];
        }
#pragma unroll
        for (int nt = 0; nt < 8; nt++) {
            int dd = wn * 64 + nt * 8 + gp;
            const uint32_t* p = sW + dd * PADH + kb + tg;
            bf[nt][0] = p[0]; bf[nt][1] = p[4];
        }
#pragma unroll
        for (int mt = 0; mt < 2; mt++)
#pragma unroll
            for (int nt = 0; nt < 8; nt++)
                MMA_TF32(acc[mt][nt], af[mt], bf[nt]);
    }

    // ---- epilogue: bias + LayerNorm + ReLU ----
    const float* sbias = sf + SM_PAR_OFF / 4;
    const float* sgam  = sbias + 128;
    const float* sbet  = sbias + 256;

    float s1[2][2] = {{0.f, 0.f}, {0.f, 0.f}};
    float s2[2][2] = {{0.f, 0.f}, {0.f, 0.f}};
#pragma unroll
    for (int mt = 0; mt < 2; mt++)
#pragma unroll
        for (int nt = 0; nt < 8; nt++) {
            int cc = wn * 64 + nt * 8 + 2 * tg;
            float b0 = sbias[cc], b1 = sbias[cc + 1];
            float v0 = acc[mt][nt][0] + b0, v1 = acc[mt][nt][1] + b1;
            float v2 = acc[mt][nt][2] + b0, v3 = acc[mt][nt][3] + b1;
            acc[mt][nt][0] = v0; acc[mt][nt][1] = v1;
            acc[mt][nt][2] = v2; acc[mt][nt][3] = v3;
            s1[mt][0] += v0 + v1;           s2[mt][0] += v0 * v0 + v1 * v1;
            s1[mt][1] += v2 + v3;           s2[mt][1] += v2 * v2 + v3 * v3;
        }
    // reduce across the 4 lanes of each group (same row)
#pragma unroll
    for (int mt = 0; mt < 2; mt++)
#pragma unroll
        for (int h = 0; h < 2; h++) {
            s1[mt][h] += __shfl_xor_sync(0xffffffffu, s1[mt][h], 1);
            s1[mt][h] += __shfl_xor_sync(0xffffffffu, s1[mt][h], 2);
            s2[mt][h] += __shfl_xor_sync(0xffffffffu, s2[mt][h], 1);
            s2[mt][h] += __shfl_xor_sync(0xffffffffu, s2[mt][h], 2);
        }
    // cross-warp (wn) combine via smem
    float* sred = sf + SM_RED_OFF / 4;
    if (tg == 0) {
#pragma unroll
        for (int mt = 0; mt < 2; mt++)
#pragma unroll
            for (int h = 0; h < 2; h++) {
                int r = wm * 32 + mt * 16 + h * 8 + gp;
                sred[r * 4 + wn * 2 + 0] = s1[mt][h];
                sred[r * 4 + wn * 2 + 1] = s2[mt][h];
            }
    }
    __syncthreads();

    float* outBase = out + ((size_t)bt * NN + (size_t)rowTile * 128) * FF;
#pragma unroll
    for (int mt = 0; mt < 2; mt++)
#pragma unroll
        for (int h = 0; h < 2; h++) {
            int r = wm * 32 + mt * 16 + h * 8 + gp;
            float S1 = sred[r * 4 + 0] + sred[r * 4 + 2];
            float S2 = sred[r * 4 + 1] + sred[r * 4 + 3];
            float mean = S1 * (1.0f / 128.0f);
            float var  = S2 * (1.0f / 128.0f) - mean * mean;
            float inv  = rsqrtf(var + 1e-5f);
            float* orow = outBase + (size_t)r * FF;
#pragma unroll
            for (int nt = 0; nt < 8; nt++) {
                int cc = wn * 64 + nt * 8 + 2 * tg;
                float v0 = acc[mt][nt][h * 2 + 0];
                float v1 = acc[mt][nt][h * 2 + 1];
                float o0 = fmaxf((v0 - mean) * inv * sgam[cc]     + sbet[cc],     0.f);
                float o1 = fmaxf((v1 - mean) * inv * sgam[cc + 1] + sbet[cc + 1], 0.f);
                *(float2*)(orow + cc) = make_float2(o0, o1);
            }
        }
}

// ---------------- launch ----------------
extern "C" void kernel_launch(void* const* d_in, const int* in_sizes, int n_in,
                              void* d_out, int out_size) {
    const float* A     = (const float*)d_in[0];   // [8,2048,2048]
    const float* X     = (const float*)d_in[1];   // [8,2048,128]
    const float* W     = (const float*)d_in[2];   // [128,128]
    const float* bias  = (const float*)d_in[3];
    const float* gamma = (const float*)d_in[4];
    const float* beta  = (const float*)d_in[5];
    float* out = (float*)d_out;

    cudaFuncSetAttribute(fused_kernel, cudaFuncAttributeMaxDynamicSharedMemorySize, SM_TOTAL);

    xt_kernel<<<dim3(NN / 32, FF / 32, BATCH), 256>>>(X);
    fused_kernel<<<BATCH * (NN / 128), 256, SM_TOTAL>>>(A, W, bias, gamma, beta, out);
}